// round 13
// baseline (speedup 1.0000x reference)
#include <cuda_runtime.h>
#include <cuda.h>
#include <cuda_bf16.h>
#include <cstdint>

// Problem dims (fixed): B=4, S=4096, D=2048, H=5632
#define MTOK 16384
#define DDIM 2048
#define HDIM 5632
#define QEPS 1e-5f
#define RMSEPS 1e-6f

#define BM 64
#define BN 128
#define BKE 32                         // K elements per tile (bf16)
#define ROWB 64                        // bytes per smem row (32 bf16)
#define STAGES 4
#define ATILE (BM * ROWB)              // 4096
#define BTILE (BN * ROWB)              // 8192
#define STAGE_GU (ATILE + 2 * BTILE)   // 20480
#define STAGE_W3 (ATILE + BTILE)       // 12288

// ---------------- scratch (static device globals; no allocation) ----------------
__device__ __align__(16) __nv_bfloat16 g_xq[(size_t)MTOK * DDIM];
__device__ __align__(16) float  g_xdq[MTOK];
__device__ __align__(16) __nv_bfloat16 g_w1q[(size_t)HDIM * DDIM];
__device__ __align__(16) __nv_bfloat16 g_w2q[(size_t)HDIM * DDIM];
__device__ __align__(16) __nv_bfloat16 g_w3q[(size_t)DDIM * HDIM];
__device__ __align__(16) float  g_wdq[3];
__device__ __align__(16) float  g_wpart[3][1024];
__device__ __align__(16) float  g_h[(size_t)MTOK * HDIM];    // h = silu(g)*u  (fp32)
__device__ __align__(16) __nv_bfloat16 g_hq[(size_t)MTOK * HDIM];
__device__ __align__(16) float  g_hdq[MTOK];

// refined reciprocal sqrt (≈1 ulp)
__device__ __forceinline__ float rsqrt_ref(float v) {
    float r = rsqrtf(v);
    r = r * (1.5f - 0.5f * v * r * r);
    return r;
}

__device__ __forceinline__ float warp_sum(float v) {
    #pragma unroll
    for (int o = 16; o; o >>= 1) v += __shfl_xor_sync(0xffffffffu, v, o);
    return v;
}
__device__ __forceinline__ float warp_max(float v) {
    #pragma unroll
    for (int o = 16; o; o >>= 1) v = fmaxf(v, __shfl_xor_sync(0xffffffffu, v, o));
    return v;
}

// ---------------- weight |w| partial sums ----------------
__global__ void __launch_bounds__(256) wsum_partial_all(const float* __restrict__ w1,
                                                        const float* __restrict__ w2,
                                                        const float* __restrict__ w3, int n) {
    int slot = blockIdx.x >> 10;
    int blk = blockIdx.x & 1023;
    const float* w = (slot == 0) ? w1 : (slot == 1) ? w2 : w3;
    float s = 0.f;
    for (int i = blk * 256 + threadIdx.x; i < n; i += 1024 * 256)
        s += fabsf(w[i]);
    __shared__ float sm[8];
    s = warp_sum(s);
    int wid = threadIdx.x >> 5, lane = threadIdx.x & 31;
    if (lane == 0) sm[wid] = s;
    __syncthreads();
    if (wid == 0) {
        float z = (lane < 8) ? sm[lane] : 0.f;
        z = warp_sum(z);
        if (lane == 0) g_wpart[slot][blk] = z;
    }
}

// -------- fused: blocks 0-2 finish weight-scale reduce; rest do RMSNorm+quant of x --------
__global__ void __launch_bounds__(256) wfinal_actqx(const float* __restrict__ x, int n) {
    __shared__ float smS[8], smM[8], smB[2];
    int t = threadIdx.x;
    int wid = t >> 5, lane = t & 31;

    if (blockIdx.x < 3) {
        int slot = blockIdx.x;
        float s = g_wpart[slot][t] + g_wpart[slot][t + 256] +
                  g_wpart[slot][t + 512] + g_wpart[slot][t + 768];
        s = warp_sum(s);
        if (lane == 0) smS[wid] = s;
        __syncthreads();
        if (wid == 0) {
            float z = (lane < 8) ? smS[lane] : 0.f;
            z = warp_sum(z);
            if (lane == 0) g_wdq[slot] = fmaxf(z / (float)n, QEPS);
        }
        return;
    }
    int r = blockIdx.x - 3;
    size_t base = (size_t)r * DDIM;
    const float4* x4 = (const float4*)(x + base);

    float4 v0 = x4[t];
    float4 v1 = x4[t + 256];
    float ss = v0.x * v0.x + v0.y * v0.y + v0.z * v0.z + v0.w * v0.w +
               v1.x * v1.x + v1.y * v1.y + v1.z * v1.z + v1.w * v1.w;
    ss = warp_sum(ss);
    if (lane == 0) smS[wid] = ss;
    __syncthreads();
    if (wid == 0) {
        float z = (lane < 8) ? smS[lane] : 0.f;
        z = warp_sum(z);
        if (lane == 0) smB[0] = z;
    }
    __syncthreads();
    float rr = rsqrt_ref(smB[0] / (float)DDIM + RMSEPS);

    // per-element |v*rr| then max (matches reference rounding)
    float am = fmaxf(fmaxf(fabsf(v0.x * rr), fabsf(v0.y * rr)),
                     fmaxf(fabsf(v0.z * rr), fabsf(v0.w * rr)));
    am = fmaxf(am, fmaxf(fmaxf(fabsf(v1.x * rr), fabsf(v1.y * rr)),
                         fmaxf(fabsf(v1.z * rr), fabsf(v1.w * rr))));
    am = warp_max(am);
    if (lane == 0) smM[wid] = am;
    __syncthreads();
    if (wid == 0) {
        float z = (lane < 8) ? smM[lane] : 0.f;
        z = warp_max(z);
        if (lane == 0) smB[1] = z;
    }
    __syncthreads();
    float anc = fmaxf(smB[1], QEPS);
    float sc = 127.0f / anc;
    float rs = rr * sc;

    __nv_bfloat162* q2 = (__nv_bfloat162*)(g_xq + base);
    int q0, q1;
    q0 = max(-128, min(127, (int)rintf(v0.x * rs)));
    q1 = max(-128, min(127, (int)rintf(v0.y * rs)));
    q2[2 * t] = __floats2bfloat162_rn((float)q0, (float)q1);
    q0 = max(-128, min(127, (int)rintf(v0.z * rs)));
    q1 = max(-128, min(127, (int)rintf(v0.w * rs)));
    q2[2 * t + 1] = __floats2bfloat162_rn((float)q0, (float)q1);
    q0 = max(-128, min(127, (int)rintf(v1.x * rs)));
    q1 = max(-128, min(127, (int)rintf(v1.y * rs)));
    q2[2 * (t + 256)] = __floats2bfloat162_rn((float)q0, (float)q1);
    q0 = max(-128, min(127, (int)rintf(v1.z * rs)));
    q1 = max(-128, min(127, (int)rintf(v1.w * rs)));
    q2[2 * (t + 256) + 1] = __floats2bfloat162_rn((float)q0, (float)q1);

    if (t == 0) g_xdq[r] = anc * (1.0f / 127.0f);
}

// ---------------- ternary weight quant -> bf16 (vectorized) ----------------
__global__ void __launch_bounds__(256) wquant_all(const float* __restrict__ w1,
                                                  const float* __restrict__ w2,
                                                  const float* __restrict__ w3, int n4) {
    int slot = blockIdx.y;
    const float4* w = (const float4*)((slot == 0) ? w1 : (slot == 1) ? w2 : w3);
    __nv_bfloat162* out = (__nv_bfloat162*)((slot == 0) ? g_w1q : (slot == 1) ? g_w2q : g_w3q);
    float sc = 1.0f / g_wdq[slot];
    int i = blockIdx.x * 256 + threadIdx.x;
    if (i < n4) {
        float4 v = w[i];
        int a0 = max(-1, min(1, (int)rintf(v.x * sc)));
        int a1 = max(-1, min(1, (int)rintf(v.y * sc)));
        int a2 = max(-1, min(1, (int)rintf(v.z * sc)));
        int a3 = max(-1, min(1, (int)rintf(v.w * sc)));
        out[2 * i]     = __floats2bfloat162_rn((float)a0, (float)a1);
        out[2 * i + 1] = __floats2bfloat162_rn((float)a2, (float)a3);
    }
}

// ------- RMSNorm + quant of h: row held in registers (11 x float2/thread) ----------
__global__ void __launch_bounds__(256) actq_h() {
    __shared__ float smS[8], smM[8], smB[2];
    int t = threadIdx.x;
    int wid = t >> 5, lane = t & 31;
    int r = blockIdx.x;
    size_t base = (size_t)r * HDIM;
    const float2* h2 = (const float2*)(g_h + base);   // 2816 float2, 11 per thread

    float2 va[11];
    float ss = 0.f;
    #pragma unroll
    for (int k = 0; k < 11; k++) {
        float2 v = h2[t + k * 256];
        va[k] = v;
        ss += v.x * v.x + v.y * v.y;
    }
    ss = warp_sum(ss);
    if (lane == 0) smS[wid] = ss;
    __syncthreads();
    if (wid == 0) {
        float z = (lane < 8) ? smS[lane] : 0.f;
        z = warp_sum(z);
        if (lane == 0) smB[0] = z;
    }
    __syncthreads();
    float rr = rsqrt_ref(smB[0] / (float)HDIM + RMSEPS);

    float am = 0.f;
    #pragma unroll
    for (int k = 0; k < 11; k++)
        am = fmaxf(am, fmaxf(fabsf(va[k].x * rr), fabsf(va[k].y * rr)));
    am = warp_max(am);
    if (lane == 0) smM[wid] = am;
    __syncthreads();
    if (wid == 0) {
        float z = (lane < 8) ? smM[lane] : 0.f;
        z = warp_max(z);
        if (lane == 0) smB[1] = z;
    }
    __syncthreads();
    float anc = fmaxf(smB[1], QEPS);
    float sc = 127.0f / anc;
    float rs = rr * sc;

    __nv_bfloat162* q2 = (__nv_bfloat162*)(g_hq + base);
    #pragma unroll
    for (int k = 0; k < 11; k++) {
        int q0 = max(-128, min(127, (int)rintf(va[k].x * rs)));
        int q1 = max(-128, min(127, (int)rintf(va[k].y * rs)));
        q2[t + k * 256] = __floats2bfloat162_rn((float)q0, (float)q1);
    }
    if (t == 0) g_hdq[r] = anc * (1.0f / 127.0f);
}

// ================= bf16 GEMM machinery =================
#define MBAR_INIT(a, c) \
    asm volatile("mbarrier.init.shared.b64 [%0], %1;" ::"r"(a), "r"(c) : "memory")
#define MBAR_EXPECT(a, b) \
    asm volatile("mbarrier.arrive.expect_tx.shared.b64 _, [%0], %1;" ::"r"(a), "r"(b) : "memory")
#define MBAR_ARRIVE(a) \
    asm volatile("mbarrier.arrive.shared.b64 _, [%0];" ::"r"(a) : "memory")
#define TMA2D(dst, map, cx, cy, mb) \
    asm volatile("cp.async.bulk.tensor.2d.shared::cta.global.tile.mbarrier::complete_tx::bytes " \
                 "[%0], [%1, {%2, %3}], [%4];" ::"r"(dst), "l"(map), "r"(cx), "r"(cy), "r"(mb) : "memory")

__device__ __forceinline__ void mbar_wait(uint32_t addr, uint32_t parity) {
    uint32_t done;
    asm volatile(
        "{\n\t.reg .pred p;\n\t"
        "mbarrier.try_wait.parity.acquire.cta.shared::cta.b64 p, [%1], %2;\n\t"
        "selp.b32 %0, 1, 0, p;\n\t}"
        : "=r"(done) : "r"(addr), "r"(parity) : "memory");
    if (!done) {
        asm volatile(
            "{\n\t.reg .pred P1;\n\t"
            "WL_%=:\n\t"
            "mbarrier.try_wait.parity.acquire.cta.shared::cta.b64 P1, [%0], %1, 0x989680;\n\t"
            "@P1 bra.uni WD_%=;\n\t"
            "bra.uni WL_%=;\n\t"
            "WD_%=:\n\t}"
            ::"r"(addr), "r"(parity) : "memory");
    }
}

__device__ __forceinline__ void mma_bf16(float* c, const uint32_t* a, uint32_t b0, uint32_t b1) {
    asm volatile(
        "mma.sync.aligned.m16n8k16.row.col.f32.bf16.bf16.f32 "
        "{%0,%1,%2,%3}, {%4,%5,%6,%7}, {%8,%9}, {%0,%1,%2,%3};\n"
        : "+f"(c[0]), "+f"(c[1]), "+f"(c[2]), "+f"(c[3])
        : "r"(a[0]), "r"(a[1]), "r"(a[2]), "r"(a[3]), "r"(b0), "r"(b1));
}

__device__ __forceinline__ void ldsm4(uint32_t& r0, uint32_t& r1, uint32_t& r2, uint32_t& r3,
                                      uint32_t a) {
    asm volatile("ldmatrix.sync.aligned.m8n8.x4.shared.b16 {%0,%1,%2,%3}, [%4];"
                 : "=r"(r0), "=r"(r1), "=r"(r2), "=r"(r3) : "r"(a));
}

// ---- fused gate/up GEMM: h = silu(xq@w1^T) * (xq@w2^T)  (writes fp32) ----
// 256 threads, warp grid 2(M) x 4(N), warp tile 32x32, 2 CTA/SM
__global__ void __launch_bounds__(256, 2) gemm_gateup(
        const __grid_constant__ CUtensorMap tmA,
        const __grid_constant__ CUtensorMap tmB0,
        const __grid_constant__ CUtensorMap tmB1) {
    extern __shared__ char dsm[];
    __shared__ __align__(8) uint64_t s_full[STAGES];
    __shared__ __align__(8) uint64_t s_empty[STAGES];

    int tid = threadIdx.x;
    int lane = tid & 31;
    int warp = tid >> 5;
    int wm = warp & 1;
    int wn = warp >> 1;
    int g = lane >> 2;
    int t = lane & 3;
    int grp = lane >> 3;
    int lr = lane & 7;
    int m0blk = blockIdx.y * BM;
    int n0blk = blockIdx.x * BN;
    const int NT = DDIM / BKE;   // 64

    uint32_t dbase = (uint32_t)__cvta_generic_to_shared(dsm);
    dbase = (dbase + 1023) & ~1023u;
    uint32_t fullu = (uint32_t)__cvta_generic_to_shared(&s_full[0]);
    uint32_t emptyu = (uint32_t)__cvta_generic_to_shared(&s_empty[0]);

    if (tid == 0) {
        #pragma unroll
        for (int s = 0; s < STAGES; s++) {
            MBAR_INIT(fullu + s * 8, 1);
            MBAR_INIT(emptyu + s * 8, 8);
        }
        asm volatile("fence.proxy.async.shared::cta;" ::: "memory");
    }
    __syncthreads();

    if (tid == 0) {
        #pragma unroll
        for (int s = 0; s < STAGES; s++) {
            MBAR_EXPECT(fullu + s * 8, STAGE_GU);
            uint32_t sb = dbase + s * STAGE_GU;
            TMA2D(sb, &tmA, s * BKE, m0blk, fullu + s * 8);
            TMA2D(sb + ATILE, &tmB0, s * BKE, n0blk, fullu + s * 8);
            TMA2D(sb + ATILE + BTILE, &tmB1, s * BKE, n0blk, fullu + s * 8);
        }
    }

    // ldmatrix byte offsets (SW64: chunk c stored at c ^ ((row>>1)&3))
    int aoff[2][2];
    #pragma unroll
    for (int mi = 0; mi < 2; mi++)
        #pragma unroll
        for (int ks = 0; ks < 2; ks++) {
            int row = wm * 32 + mi * 16 + lr + ((grp & 1) << 3);
            int c = ks * 2 + (grp >> 1);
            aoff[mi][ks] = row * ROWB + ((c ^ ((row >> 1) & 3)) << 4);
        }
    int boff[2][2];
    #pragma unroll
    for (int p = 0; p < 2; p++)
        #pragma unroll
        for (int ks = 0; ks < 2; ks++) {
            int row = wn * 32 + p * 16 + ((grp & 1) << 3) + lr;
            int c = ks * 2 + (grp >> 1);
            boff[p][ks] = ATILE + row * ROWB + ((c ^ ((row >> 1) & 3)) << 4);
        }

    float accG[2][4][4], accU[2][4][4];
    #pragma unroll
    for (int mi = 0; mi < 2; mi++)
        #pragma unroll
        for (int ni = 0; ni < 4; ni++)
            #pragma unroll
            for (int j = 0; j < 4; j++) { accG[mi][ni][j] = 0.f; accU[mi][ni][j] = 0.f; }

    for (int kt = 0; kt < NT; kt++) {
        int st = kt & (STAGES - 1);
        uint32_t par = (uint32_t)(kt / STAGES) & 1;
        uint32_t sb = dbase + st * STAGE_GU;

        mbar_wait(fullu + st * 8, par);

        // ---- ks = 0 ----
        {
            uint32_t a[2][4];
            #pragma unroll
            for (int mi = 0; mi < 2; mi++)
                ldsm4(a[mi][0], a[mi][1], a[mi][2], a[mi][3], sb + aoff[mi][0]);
            uint32_t b[2][4];
            #pragma unroll
            for (int p = 0; p < 2; p++)
                ldsm4(b[p][0], b[p][1], b[p][2], b[p][3], sb + boff[p][0]);
            #pragma unroll
            for (int mi = 0; mi < 2; mi++)
                #pragma unroll
                for (int ni = 0; ni < 4; ni++)
                    mma_bf16(accG[mi][ni], a[mi],
                             b[ni >> 1][ni & 1], b[ni >> 1][2 + (ni & 1)]);
            uint32_t c2[2][4];
            #pragma unroll
            for (int p = 0; p < 2; p++)
                ldsm4(c2[p][0], c2[p][1], c2[p][2], c2[p][3], sb + boff[p][0] + BTILE);
            #pragma unroll
            for (int mi = 0; mi < 2; mi++)
                #pragma unroll
                for (int ni = 0; ni < 4; ni++)
                    mma_bf16(accU[mi][ni], a[mi],
                             c2[ni >> 1][ni & 1], c2[ni >> 1][2 + (ni & 1)]);
        }
        // ---- ks = 1: load everything, free the stage, then MMA ----
        {
            uint32_t a[2][4];
            #pragma unroll
            for (int mi = 0; mi < 2; mi++)
                ldsm4(a[mi][0], a[mi][1], a[mi][2], a[mi][3], sb + aoff[mi][1]);
            uint32_t b[2][4];
            #pragma unroll
            for (int p = 0; p < 2; p++)
                ldsm4(b[p][0], b[p][1], b[p][2], b[p][3], sb + boff[p][1]);
            uint32_t c2[2][4];
            #pragma unroll
            for (int p = 0; p < 2; p++)
                ldsm4(c2[p][0], c2[p][1], c2[p][2], c2[p][3], sb + boff[p][1] + BTILE);

            if (lane == 0) MBAR_ARRIVE(emptyu + st * 8);

            #pragma unroll
            for (int mi = 0; mi < 2; mi++)
                #pragma unroll
                for (int ni = 0; ni < 4; ni++)
                    mma_bf16(accG[mi][ni], a[mi],
                             b[ni >> 1][ni & 1], b[ni >> 1][2 + (ni & 1)]);
            #pragma unroll
            for (int mi = 0; mi < 2; mi++)
                #pragma unroll
                for (int ni = 0; ni < 4; ni++)
                    mma_bf16(accU[mi][ni], a[mi],
                             c2[ni >> 1][ni & 1], c2[ni >> 1][2 + (ni & 1)]);
        }

        int nkt = kt + STAGES;
        if (tid == 0 && nkt < NT) {
            mbar_wait(emptyu + st * 8, par);
            MBAR_EXPECT(fullu + st * 8, STAGE_GU);
            TMA2D(sb, &tmA, nkt * BKE, m0blk, fullu + st * 8);
            TMA2D(sb + ATILE, &tmB0, nkt * BKE, n0blk, fullu + st * 8);
            TMA2D(sb + ATILE + BTILE, &tmB1, nkt * BKE, n0blk, fullu + st * 8);
        }
    }

    // epilogue: h = silu(gate) * up -> fp32
    float wg = g_wdq[0], wu = g_wdq[1];
    #pragma unroll
    for (int mi = 0; mi < 2; mi++) {
        int r0 = m0blk + wm * 32 + mi * 16 + g;
        float x0 = g_xdq[r0], x1 = g_xdq[r0 + 8];
        float sg0 = x0 * wg, su0 = x0 * wu;
        float sg1 = x1 * wg, su1 = x1 * wu;
        #pragma unroll
        for (int ni = 0; ni < 4; ni++) {
            int c = n0blk + wn * 32 + ni * 8 + t * 2;
            float* D0 = g_h + (size_t)r0 * HDIM + c;
            float* D1 = g_h + (size_t)(r0 + 8) * HDIM + c;
            float gv, uv;
            float2 o0, o1;
            gv = accG[mi][ni][0] * sg0; uv = accU[mi][ni][0] * su0;
            o0.x = gv / (1.0f + expf(-gv)) * uv;
            gv = accG[mi][ni][1] * sg0; uv = accU[mi][ni][1] * su0;
            o0.y = gv / (1.0f + expf(-gv)) * uv;
            gv = accG[mi][ni][2] * sg1; uv = accU[mi][ni][2] * su1;
            o1.x = gv / (1.0f + expf(-gv)) * uv;
            gv = accG[mi][ni][3] * sg1; uv = accU[mi][ni][3] * su1;
            o1.y = gv / (1.0f + expf(-gv)) * uv;
            *(float2*)D0 = o0;
            *(float2*)D1 = o1;
        }
    }
}

// ---- w3 GEMM: out = hq @ w3^T (fp32 out), 256 threads, 2x4 warps, 3 CTA/SM ----
__global__ void __launch_bounds__(256, 3) gemm_w3(float* __restrict__ outext,
        const __grid_constant__ CUtensorMap tmA,
        const __grid_constant__ CUtensorMap tmB) {
    extern __shared__ char dsm[];
    __shared__ __align__(8) uint64_t s_full[STAGES];
    __shared__ __align__(8) uint64_t s_empty[STAGES];

    int tid = threadIdx.x;
    int lane = tid & 31;
    int warp = tid >> 5;
    int wm = warp & 1;
    int wn = warp >> 1;
    int g = lane >> 2;
    int t = lane & 3;
    int grp = lane >> 3;
    int lr = lane & 7;
    int m0blk = blockIdx.y * BM;
    int n0blk = blockIdx.x * BN;
    const int NT = HDIM / BKE;   // 176

    uint32_t dbase = (uint32_t)__cvta_generic_to_shared(dsm);
    dbase = (dbase + 1023) & ~1023u;
    uint32_t fullu = (uint32_t)__cvta_generic_to_shared(&s_full[0]);
    uint32_t emptyu = (uint32_t)__cvta_generic_to_shared(&s_empty[0]);

    if (tid == 0) {
        #pragma unroll
        for (int s = 0; s < STAGES; s++) {
            MBAR_INIT(fullu + s * 8, 1);
            MBAR_INIT(emptyu + s * 8, 8);
        }
        asm volatile("fence.proxy.async.shared::cta;" ::: "memory");
    }
    __syncthreads();

    if (tid == 0) {
        #pragma unroll
        for (int s = 0; s < STAGES; s++) {
            MBAR_EXPECT(fullu + s * 8, STAGE_W3);
            uint32_t sb = dbase + s * STAGE_W3;
            TMA2D(sb, &tmA, s * BKE, m0blk, fullu + s * 8);
            TMA2D(sb + ATILE, &tmB, s * BKE, n0blk, fullu + s * 8);
        }
    }

    int aoff[2][2];
    #pragma unroll
    for (int mi = 0; mi < 2; mi++)
        #pragma unroll
        for (int ks = 0; ks < 2; ks++) {
            int row = wm * 32 + mi * 16 + lr + ((grp & 1) << 3);
            int c = ks * 2 + (grp >> 1);
            aoff[mi][ks] = row * ROWB + ((c ^ ((row >> 1) & 3)) << 4);
        }
    int boff[2][2];
    #pragma unroll
    for (int p = 0; p < 2; p++)
        #pragma unroll
        for (int ks = 0; ks < 2; ks++) {
            int row = wn * 32 + p * 16 + ((grp & 1) << 3) + lr;
            int c = ks * 2 + (grp >> 1);
            boff[p][ks] = ATILE + row * ROWB + ((c ^ ((row >> 1) & 3)) << 4);
        }

    float acc[2][4][4];
    #pragma unroll
    for (int mi = 0; mi < 2; mi++)
        #pragma unroll
        for (int ni = 0; ni < 4; ni++)
            #pragma unroll
            for (int j = 0; j < 4; j++) acc[mi][ni][j] = 0.f;

    for (int kt = 0; kt < NT; kt++) {
        int st = kt & (STAGES - 1);
        uint32_t par = (uint32_t)(kt / STAGES) & 1;
        uint32_t sb = dbase + st * STAGE_W3;

        mbar_wait(fullu + st * 8, par);

        // ---- ks = 0 ----
        {
            uint32_t a[2][4];
            uint32_t b[2][4];
            #pragma unroll
            for (int mi = 0; mi < 2; mi++)
                ldsm4(a[mi][0], a[mi][1], a[mi][2], a[mi][3], sb + aoff[mi][0]);
            #pragma unroll
            for (int p = 0; p < 2; p++)
                ldsm4(b[p][0], b[p][1], b[p][2], b[p][3], sb + boff[p][0]);
            #pragma unroll
            for (int mi = 0; mi < 2; mi++)
                #pragma unroll
                for (int ni = 0; ni < 4; ni++)
                    mma_bf16(acc[mi][ni], a[mi],
                             b[ni >> 1][ni & 1], b[ni >> 1][2 + (ni & 1)]);
        }
        // ---- ks = 1: loads, free stage, then MMA ----
        {
            uint32_t a[2][4];
            uint32_t b[2][4];
            #pragma unroll
            for (int mi = 0; mi < 2; mi++)
                ldsm4(a[mi][0], a[mi][1], a[mi][2], a[mi][3], sb + aoff[mi][1]);
            #pragma unroll
            for (int p = 0; p < 2; p++)
                ldsm4(b[p][0], b[p][1], b[p][2], b[p][3], sb + boff[p][1]);

            if (lane == 0) MBAR_ARRIVE(emptyu + st * 8);

            #pragma unroll
            for (int mi = 0; mi < 2; mi++)
                #pragma unroll
                for (int ni = 0; ni < 4; ni++)
                    mma_bf16(acc[mi][ni], a[mi],
                             b[ni >> 1][ni & 1], b[ni >> 1][2 + (ni & 1)]);
        }

        int nkt = kt + STAGES;
        if (tid == 0 && nkt < NT) {
            mbar_wait(emptyu + st * 8, par);
            MBAR_EXPECT(fullu + st * 8, STAGE_W3);
            TMA2D(sb, &tmA, nkt * BKE, m0blk, fullu + st * 8);
            TMA2D(sb + ATILE, &tmB, nkt * BKE, n0blk, fullu + st * 8);
        }
    }

    float wq = g_wdq[2];
    #pragma unroll
    for (int mi = 0; mi < 2; mi++) {
        int r0 = m0blk + wm * 32 + mi * 16 + g;
        float s0 = g_hdq[r0] * wq;
        float s1 = g_hdq[r0 + 8] * wq;
        #pragma unroll
        for (int ni = 0; ni < 4; ni++) {
            int c = n0blk + wn * 32 + ni * 8 + t * 2;
            float* C0 = outext + (size_t)r0 * DDIM + c;
            float* C1 = outext + (size_t)(r0 + 8) * DDIM + c;
            *(float2*)C0 = make_float2(acc[mi][ni][0] * s0, acc[mi][ni][1] * s0);
            *(float2*)C1 = make_float2(acc[mi][ni][2] * s1, acc[mi][ni][3] * s1);
        }
    }
}

// ---------------- host: tensormap encode via runtime-resolved driver entry ----------------
typedef CUresult (*PFN_tmEncode)(CUtensorMap*, CUtensorMapDataType, cuuint32_t, void*,
                                 const cuuint64_t*, const cuuint64_t*, const cuuint32_t*,
                                 const cuuint32_t*, CUtensorMapInterleave, CUtensorMapSwizzle,
                                 CUtensorMapL2promotion, CUtensorMapFloatOOBfill);

static PFN_tmEncode get_encoder() {
    void* fp = nullptr;
    cudaDriverEntryPointQueryResult qr;
#if CUDART_VERSION >= 12050
    cudaGetDriverEntryPointByVersion("cuTensorMapEncodeTiled", &fp, 12000, cudaEnableDefault, &qr);
#else
    cudaGetDriverEntryPoint("cuTensorMapEncodeTiled", &fp, cudaEnableDefault, &qr);
#endif
    return (PFN_tmEncode)fp;
}

static void make_map(PFN_tmEncode enc, CUtensorMap* m, void* base, uint64_t kdim, uint64_t rows,
                     uint32_t boxRows) {
    cuuint64_t dims[2] = {kdim, rows};
    cuuint64_t strides[1] = {kdim * 2};       // bytes (bf16)
    cuuint32_t box[2] = {BKE, boxRows};
    cuuint32_t es[2] = {1, 1};
    enc(m, CU_TENSOR_MAP_DATA_TYPE_BFLOAT16, 2, base, dims, strides, box, es,
        CU_TENSOR_MAP_INTERLEAVE_NONE, CU_TENSOR_MAP_SWIZZLE_64B,
        CU_TENSOR_MAP_L2_PROMOTION_L2_128B, CU_TENSOR_MAP_FLOAT_OOB_FILL_NONE);
}

// ---------------- launch ----------------
extern "C" void kernel_launch(void* const* d_in, const int* in_sizes, int n_in,
                              void* d_out, int out_size) {
    const float* x  = (const float*)d_in[0];
    const float* w1 = (const float*)d_in[1];
    const float* w2 = (const float*)d_in[2];
    const float* w3 = (const float*)d_in[3];
    float* out = (float*)d_out;

    PFN_tmEncode enc = get_encoder();
    void *p_xq, *p_w1, *p_w2, *p_w3, *p_hq;
    cudaGetSymbolAddress(&p_xq, g_xq);
    cudaGetSymbolAddress(&p_w1, g_w1q);
    cudaGetSymbolAddress(&p_w2, g_w2q);
    cudaGetSymbolAddress(&p_w3, g_w3q);
    cudaGetSymbolAddress(&p_hq, g_hq);

    CUtensorMap tm_xq, tm_w1, tm_w2, tm_w3, tm_hq;
    make_map(enc, &tm_xq, p_xq, DDIM, MTOK, BM);
    make_map(enc, &tm_w1, p_w1, DDIM, HDIM, BN);
    make_map(enc, &tm_w2, p_w2, DDIM, HDIM, BN);
    make_map(enc, &tm_w3, p_w3, HDIM, DDIM, BN);
    make_map(enc, &tm_hq, p_hq, HDIM, MTOK, BM);

    const int smemGU = STAGES * STAGE_GU + 1024;   // 82944
    const int smemW3 = STAGES * STAGE_W3 + 1024;   // 50176
    cudaFuncSetAttribute(gemm_gateup, cudaFuncAttributeMaxDynamicSharedMemorySize, smemGU);
    cudaFuncSetAttribute(gemm_w3, cudaFuncAttributeMaxDynamicSharedMemorySize, smemW3);

    const int nW = HDIM * DDIM;
    wsum_partial_all<<<3072, 256>>>(w1, w2, w3, nW);                 // 1
    wfinal_actqx<<<MTOK + 3, 256>>>(x, nW);                          // 2
    dim3 gq((nW / 4 + 255) / 256, 3);
    wquant_all<<<gq, 256>>>(w1, w2, w3, nW / 4);                     // 3

    dim3 ggu(HDIM / BN, MTOK / BM);
    gemm_gateup<<<ggu, 256, smemGU>>>(tm_xq, tm_w1, tm_w2);          // 4

    actq_h<<<MTOK, 256>>>();                                         // 5

    dim3 gw3(DDIM / BN, MTOK / BM);
    gemm_w3<<<gw3, 256, smemW3>>>(out, tm_hq, tm_w3);                // 6
}

// round 14
// speedup vs baseline: 1.0163x; 1.0163x over previous
#include <cuda_runtime.h>
#include <cuda.h>
#include <cuda_bf16.h>
#include <cstdint>

// Problem dims (fixed): B=4, S=4096, D=2048, H=5632
#define MTOK 16384
#define DDIM 2048
#define HDIM 5632
#define QEPS 1e-5f
#define RMSEPS 1e-6f

#define BM 64
#define BN 128
#define BKE 32                         // K elements per tile (bf16)
#define ROWB 64                        // bytes per smem row (32 bf16)
#define STAGES 4
#define ATILE (BM * ROWB)              // 4096
#define BTILE (BN * ROWB)              // 8192
#define STAGE_GU (ATILE + 2 * BTILE)   // 20480
#define STAGE_W3 (ATILE + BTILE)       // 12288

// ---------------- scratch (static device globals; no allocation) ----------------
__device__ __align__(16) __nv_bfloat16 g_xq[(size_t)MTOK * DDIM];
__device__ __align__(16) float  g_xdq[MTOK];
__device__ __align__(16) __nv_bfloat16 g_w1q[(size_t)HDIM * DDIM];
__device__ __align__(16) __nv_bfloat16 g_w2q[(size_t)HDIM * DDIM];
__device__ __align__(16) __nv_bfloat16 g_w3q[(size_t)DDIM * HDIM];
__device__ __align__(16) float  g_wdq[3];
__device__ __align__(16) float  g_wpart[3][1024];
__device__ __align__(16) float  g_h[(size_t)MTOK * HDIM];    // h = silu(g)*u  (fp32)
__device__ __align__(16) __nv_bfloat16 g_hq[(size_t)MTOK * HDIM];
__device__ __align__(16) float  g_hdq[MTOK];

// refined reciprocal sqrt (≈1 ulp)
__device__ __forceinline__ float rsqrt_ref(float v) {
    float r = rsqrtf(v);
    r = r * (1.5f - 0.5f * v * r * r);
    return r;
}

__device__ __forceinline__ float warp_sum(float v) {
    #pragma unroll
    for (int o = 16; o; o >>= 1) v += __shfl_xor_sync(0xffffffffu, v, o);
    return v;
}
__device__ __forceinline__ float warp_max(float v) {
    #pragma unroll
    for (int o = 16; o; o >>= 1) v = fmaxf(v, __shfl_xor_sync(0xffffffffu, v, o));
    return v;
}

// ---------------- weight |w| partial sums ----------------
__global__ void __launch_bounds__(256) wsum_partial_all(const float* __restrict__ w1,
                                                        const float* __restrict__ w2,
                                                        const float* __restrict__ w3, int n) {
    int slot = blockIdx.x >> 10;
    int blk = blockIdx.x & 1023;
    const float* w = (slot == 0) ? w1 : (slot == 1) ? w2 : w3;
    float s = 0.f;
    for (int i = blk * 256 + threadIdx.x; i < n; i += 1024 * 256)
        s += fabsf(w[i]);
    __shared__ float sm[8];
    s = warp_sum(s);
    int wid = threadIdx.x >> 5, lane = threadIdx.x & 31;
    if (lane == 0) sm[wid] = s;
    __syncthreads();
    if (wid == 0) {
        float z = (lane < 8) ? sm[lane] : 0.f;
        z = warp_sum(z);
        if (lane == 0) g_wpart[slot][blk] = z;
    }
}

// -------- fused: blocks 0-2 finish weight-scale reduce; rest do RMSNorm+quant of x --------
__global__ void __launch_bounds__(256) wfinal_actqx(const float* __restrict__ x, int n) {
    __shared__ float smS[8], smM[8], smB[2];
    int t = threadIdx.x;
    int wid = t >> 5, lane = t & 31;

    if (blockIdx.x < 3) {
        int slot = blockIdx.x;
        float s = g_wpart[slot][t] + g_wpart[slot][t + 256] +
                  g_wpart[slot][t + 512] + g_wpart[slot][t + 768];
        s = warp_sum(s);
        if (lane == 0) smS[wid] = s;
        __syncthreads();
        if (wid == 0) {
            float z = (lane < 8) ? smS[lane] : 0.f;
            z = warp_sum(z);
            if (lane == 0) g_wdq[slot] = fmaxf(z / (float)n, QEPS);
        }
        return;
    }
    int r = blockIdx.x - 3;
    size_t base = (size_t)r * DDIM;
    const float4* x4 = (const float4*)(x + base);

    float4 v0 = x4[t];
    float4 v1 = x4[t + 256];
    float ss = v0.x * v0.x + v0.y * v0.y + v0.z * v0.z + v0.w * v0.w +
               v1.x * v1.x + v1.y * v1.y + v1.z * v1.z + v1.w * v1.w;
    ss = warp_sum(ss);
    if (lane == 0) smS[wid] = ss;
    __syncthreads();
    if (wid == 0) {
        float z = (lane < 8) ? smS[lane] : 0.f;
        z = warp_sum(z);
        if (lane == 0) smB[0] = z;
    }
    __syncthreads();
    float rr = rsqrt_ref(smB[0] / (float)DDIM + RMSEPS);

    float am = fmaxf(fmaxf(fabsf(v0.x * rr), fabsf(v0.y * rr)),
                     fmaxf(fabsf(v0.z * rr), fabsf(v0.w * rr)));
    am = fmaxf(am, fmaxf(fmaxf(fabsf(v1.x * rr), fabsf(v1.y * rr)),
                         fmaxf(fabsf(v1.z * rr), fabsf(v1.w * rr))));
    am = warp_max(am);
    if (lane == 0) smM[wid] = am;
    __syncthreads();
    if (wid == 0) {
        float z = (lane < 8) ? smM[lane] : 0.f;
        z = warp_max(z);
        if (lane == 0) smB[1] = z;
    }
    __syncthreads();
    float anc = fmaxf(smB[1], QEPS);
    float sc = 127.0f / anc;
    float rs = rr * sc;

    __nv_bfloat162* q2 = (__nv_bfloat162*)(g_xq + base);
    int q0, q1;
    q0 = max(-128, min(127, (int)rintf(v0.x * rs)));
    q1 = max(-128, min(127, (int)rintf(v0.y * rs)));
    q2[2 * t] = __floats2bfloat162_rn((float)q0, (float)q1);
    q0 = max(-128, min(127, (int)rintf(v0.z * rs)));
    q1 = max(-128, min(127, (int)rintf(v0.w * rs)));
    q2[2 * t + 1] = __floats2bfloat162_rn((float)q0, (float)q1);
    q0 = max(-128, min(127, (int)rintf(v1.x * rs)));
    q1 = max(-128, min(127, (int)rintf(v1.y * rs)));
    q2[2 * (t + 256)] = __floats2bfloat162_rn((float)q0, (float)q1);
    q0 = max(-128, min(127, (int)rintf(v1.z * rs)));
    q1 = max(-128, min(127, (int)rintf(v1.w * rs)));
    q2[2 * (t + 256) + 1] = __floats2bfloat162_rn((float)q0, (float)q1);

    if (t == 0) g_xdq[r] = anc * (1.0f / 127.0f);
}

// ---------------- ternary weight quant -> bf16 (vectorized) ----------------
__global__ void __launch_bounds__(256) wquant_all(const float* __restrict__ w1,
                                                  const float* __restrict__ w2,
                                                  const float* __restrict__ w3, int n4) {
    int slot = blockIdx.y;
    const float4* w = (const float4*)((slot == 0) ? w1 : (slot == 1) ? w2 : w3);
    __nv_bfloat162* out = (__nv_bfloat162*)((slot == 0) ? g_w1q : (slot == 1) ? g_w2q : g_w3q);
    float sc = 1.0f / g_wdq[slot];
    int i = blockIdx.x * 256 + threadIdx.x;
    if (i < n4) {
        float4 v = w[i];
        int a0 = max(-1, min(1, (int)rintf(v.x * sc)));
        int a1 = max(-1, min(1, (int)rintf(v.y * sc)));
        int a2 = max(-1, min(1, (int)rintf(v.z * sc)));
        int a3 = max(-1, min(1, (int)rintf(v.w * sc)));
        out[2 * i]     = __floats2bfloat162_rn((float)a0, (float)a1);
        out[2 * i + 1] = __floats2bfloat162_rn((float)a2, (float)a3);
    }
}

// ------- RMSNorm + quant of h: row held in registers (11 x float2/thread) ----------
__global__ void __launch_bounds__(256) actq_h() {
    __shared__ float smS[8], smM[8], smB[2];
    int t = threadIdx.x;
    int wid = t >> 5, lane = t & 31;
    int r = blockIdx.x;
    size_t base = (size_t)r * HDIM;
    const float2* h2 = (const float2*)(g_h + base);   // 2816 float2, 11 per thread

    float2 va[11];
    float ss = 0.f;
    #pragma unroll
    for (int k = 0; k < 11; k++) {
        float2 v = h2[t + k * 256];
        va[k] = v;
        ss += v.x * v.x + v.y * v.y;
    }
    ss = warp_sum(ss);
    if (lane == 0) smS[wid] = ss;
    __syncthreads();
    if (wid == 0) {
        float z = (lane < 8) ? smS[lane] : 0.f;
        z = warp_sum(z);
        if (lane == 0) smB[0] = z;
    }
    __syncthreads();
    float rr = rsqrt_ref(smB[0] / (float)HDIM + RMSEPS);

    float am = 0.f;
    #pragma unroll
    for (int k = 0; k < 11; k++)
        am = fmaxf(am, fmaxf(fabsf(va[k].x * rr), fabsf(va[k].y * rr)));
    am = warp_max(am);
    if (lane == 0) smM[wid] = am;
    __syncthreads();
    if (wid == 0) {
        float z = (lane < 8) ? smM[lane] : 0.f;
        z = warp_max(z);
        if (lane == 0) smB[1] = z;
    }
    __syncthreads();
    float anc = fmaxf(smB[1], QEPS);
    float sc = 127.0f / anc;
    float rs = rr * sc;

    __nv_bfloat162* q2 = (__nv_bfloat162*)(g_hq + base);
    #pragma unroll
    for (int k = 0; k < 11; k++) {
        int q0 = max(-128, min(127, (int)rintf(va[k].x * rs)));
        int q1 = max(-128, min(127, (int)rintf(va[k].y * rs)));
        q2[t + k * 256] = __floats2bfloat162_rn((float)q0, (float)q1);
    }
    if (t == 0) g_hdq[r] = anc * (1.0f / 127.0f);
}

// ================= bf16 GEMM machinery =================
#define MBAR_INIT(a, c) \
    asm volatile("mbarrier.init.shared.b64 [%0], %1;" ::"r"(a), "r"(c) : "memory")
#define MBAR_EXPECT(a, b) \
    asm volatile("mbarrier.arrive.expect_tx.shared.b64 _, [%0], %1;" ::"r"(a), "r"(b) : "memory")
#define MBAR_ARRIVE(a) \
    asm volatile("mbarrier.arrive.shared.b64 _, [%0];" ::"r"(a) : "memory")
#define TMA2D(dst, map, cx, cy, mb) \
    asm volatile("cp.async.bulk.tensor.2d.shared::cta.global.tile.mbarrier::complete_tx::bytes " \
                 "[%0], [%1, {%2, %3}], [%4];" ::"r"(dst), "l"(map), "r"(cx), "r"(cy), "r"(mb) : "memory")

__device__ __forceinline__ void mbar_wait(uint32_t addr, uint32_t parity) {
    uint32_t done;
    asm volatile(
        "{\n\t.reg .pred p;\n\t"
        "mbarrier.try_wait.parity.acquire.cta.shared::cta.b64 p, [%1], %2;\n\t"
        "selp.b32 %0, 1, 0, p;\n\t}"
        : "=r"(done) : "r"(addr), "r"(parity) : "memory");
    if (!done) {
        asm volatile(
            "{\n\t.reg .pred P1;\n\t"
            "WL_%=:\n\t"
            "mbarrier.try_wait.parity.acquire.cta.shared::cta.b64 P1, [%0], %1, 0x989680;\n\t"
            "@P1 bra.uni WD_%=;\n\t"
            "bra.uni WL_%=;\n\t"
            "WD_%=:\n\t}"
            ::"r"(addr), "r"(parity) : "memory");
    }
}

__device__ __forceinline__ void mma_bf16(float* c, const uint32_t* a, uint32_t b0, uint32_t b1) {
    asm volatile(
        "mma.sync.aligned.m16n8k16.row.col.f32.bf16.bf16.f32 "
        "{%0,%1,%2,%3}, {%4,%5,%6,%7}, {%8,%9}, {%0,%1,%2,%3};\n"
        : "+f"(c[0]), "+f"(c[1]), "+f"(c[2]), "+f"(c[3])
        : "r"(a[0]), "r"(a[1]), "r"(a[2]), "r"(a[3]), "r"(b0), "r"(b1));
}

__device__ __forceinline__ void ldsm4(uint32_t& r0, uint32_t& r1, uint32_t& r2, uint32_t& r3,
                                      uint32_t a) {
    asm volatile("ldmatrix.sync.aligned.m8n8.x4.shared.b16 {%0,%1,%2,%3}, [%4];"
                 : "=r"(r0), "=r"(r1), "=r"(r2), "=r"(r3) : "r"(a));
}

// ---- fused gate/up GEMM: h = silu(xq@w1^T) * (xq@w2^T)  (writes fp32) ----
// 256 threads, warp grid 2(M) x 4(N), warp tile 32x32, 2 CTA/SM, 4x-unrolled mainloop
__global__ void __launch_bounds__(256, 2) gemm_gateup(
        const __grid_constant__ CUtensorMap tmA,
        const __grid_constant__ CUtensorMap tmB0,
        const __grid_constant__ CUtensorMap tmB1) {
    extern __shared__ char dsm[];
    __shared__ __align__(8) uint64_t s_full[STAGES];
    __shared__ __align__(8) uint64_t s_empty[STAGES];

    int tid = threadIdx.x;
    int lane = tid & 31;
    int warp = tid >> 5;
    int wm = warp & 1;
    int wn = warp >> 1;
    int g = lane >> 2;
    int t = lane & 3;
    int grp = lane >> 3;
    int lr = lane & 7;
    int m0blk = blockIdx.y * BM;
    int n0blk = blockIdx.x * BN;
    const int NT = DDIM / BKE;   // 64 (16 unrolled blocks)

    uint32_t dbase = (uint32_t)__cvta_generic_to_shared(dsm);
    dbase = (dbase + 1023) & ~1023u;
    uint32_t fullu = (uint32_t)__cvta_generic_to_shared(&s_full[0]);
    uint32_t emptyu = (uint32_t)__cvta_generic_to_shared(&s_empty[0]);

    if (tid == 0) {
        #pragma unroll
        for (int s = 0; s < STAGES; s++) {
            MBAR_INIT(fullu + s * 8, 1);
            MBAR_INIT(emptyu + s * 8, 8);
        }
        asm volatile("fence.proxy.async.shared::cta;" ::: "memory");
    }
    __syncthreads();

    if (tid == 0) {
        #pragma unroll
        for (int s = 0; s < STAGES; s++) {
            MBAR_EXPECT(fullu + s * 8, STAGE_GU);
            uint32_t sb = dbase + s * STAGE_GU;
            TMA2D(sb, &tmA, s * BKE, m0blk, fullu + s * 8);
            TMA2D(sb + ATILE, &tmB0, s * BKE, n0blk, fullu + s * 8);
            TMA2D(sb + ATILE + BTILE, &tmB1, s * BKE, n0blk, fullu + s * 8);
        }
    }

    // ldmatrix byte offsets (SW64: chunk c stored at c ^ ((row>>1)&3))
    int aoff[2][2];
    #pragma unroll
    for (int mi = 0; mi < 2; mi++)
        #pragma unroll
        for (int ks = 0; ks < 2; ks++) {
            int row = wm * 32 + mi * 16 + lr + ((grp & 1) << 3);
            int c = ks * 2 + (grp >> 1);
            aoff[mi][ks] = row * ROWB + ((c ^ ((row >> 1) & 3)) << 4);
        }
    int boff[2][2];
    #pragma unroll
    for (int p = 0; p < 2; p++)
        #pragma unroll
        for (int ks = 0; ks < 2; ks++) {
            int row = wn * 32 + p * 16 + ((grp & 1) << 3) + lr;
            int c = ks * 2 + (grp >> 1);
            boff[p][ks] = ATILE + row * ROWB + ((c ^ ((row >> 1) & 3)) << 4);
        }

    float accG[2][4][4], accU[2][4][4];
    #pragma unroll
    for (int mi = 0; mi < 2; mi++)
        #pragma unroll
        for (int ni = 0; ni < 4; ni++)
            #pragma unroll
            for (int j = 0; j < 4; j++) { accG[mi][ni][j] = 0.f; accU[mi][ni][j] = 0.f; }

    const int NB = NT / STAGES;   // 16
    for (int kb = 0; kb < NB; kb++) {
        uint32_t par = (uint32_t)kb & 1;
        #pragma unroll
        for (int s = 0; s < STAGES; s++) {
            uint32_t sb = dbase + s * STAGE_GU;   // compile-time stage offset

            mbar_wait(fullu + s * 8, par);

            // ---- ks = 0 ----
            {
                uint32_t a[2][4];
                #pragma unroll
                for (int mi = 0; mi < 2; mi++)
                    ldsm4(a[mi][0], a[mi][1], a[mi][2], a[mi][3], sb + aoff[mi][0]);
                uint32_t b[2][4];
                #pragma unroll
                for (int p = 0; p < 2; p++)
                    ldsm4(b[p][0], b[p][1], b[p][2], b[p][3], sb + boff[p][0]);
                #pragma unroll
                for (int mi = 0; mi < 2; mi++)
                    #pragma unroll
                    for (int ni = 0; ni < 4; ni++)
                        mma_bf16(accG[mi][ni], a[mi],
                                 b[ni >> 1][ni & 1], b[ni >> 1][2 + (ni & 1)]);
                uint32_t c2[2][4];
                #pragma unroll
                for (int p = 0; p < 2; p++)
                    ldsm4(c2[p][0], c2[p][1], c2[p][2], c2[p][3], sb + boff[p][0] + BTILE);
                #pragma unroll
                for (int mi = 0; mi < 2; mi++)
                    #pragma unroll
                    for (int ni = 0; ni < 4; ni++)
                        mma_bf16(accU[mi][ni], a[mi],
                                 c2[ni >> 1][ni & 1], c2[ni >> 1][2 + (ni & 1)]);
            }
            // ---- ks = 1: load everything, free the stage, then MMA ----
            {
                uint32_t a[2][4];
                #pragma unroll
                for (int mi = 0; mi < 2; mi++)
                    ldsm4(a[mi][0], a[mi][1], a[mi][2], a[mi][3], sb + aoff[mi][1]);
                uint32_t b[2][4];
                #pragma unroll
                for (int p = 0; p < 2; p++)
                    ldsm4(b[p][0], b[p][1], b[p][2], b[p][3], sb + boff[p][1]);
                uint32_t c2[2][4];
                #pragma unroll
                for (int p = 0; p < 2; p++)
                    ldsm4(c2[p][0], c2[p][1], c2[p][2], c2[p][3], sb + boff[p][1] + BTILE);

                if (lane == 0) MBAR_ARRIVE(emptyu + s * 8);

                #pragma unroll
                for (int mi = 0; mi < 2; mi++)
                    #pragma unroll
                    for (int ni = 0; ni < 4; ni++)
                        mma_bf16(accG[mi][ni], a[mi],
                                 b[ni >> 1][ni & 1], b[ni >> 1][2 + (ni & 1)]);
                #pragma unroll
                for (int mi = 0; mi < 2; mi++)
                    #pragma unroll
                    for (int ni = 0; ni < 4; ni++)
                        mma_bf16(accU[mi][ni], a[mi],
                                 c2[ni >> 1][ni & 1], c2[ni >> 1][2 + (ni & 1)]);
            }

            int nkt = (kb + 1) * STAGES + s;
            if (tid == 0 && nkt < NT) {
                mbar_wait(emptyu + s * 8, par);
                MBAR_EXPECT(fullu + s * 8, STAGE_GU);
                TMA2D(sb, &tmA, nkt * BKE, m0blk, fullu + s * 8);
                TMA2D(sb + ATILE, &tmB0, nkt * BKE, n0blk, fullu + s * 8);
                TMA2D(sb + ATILE + BTILE, &tmB1, nkt * BKE, n0blk, fullu + s * 8);
            }
        }
    }

    // epilogue: h = silu(gate) * up -> fp32
    float wg = g_wdq[0], wu = g_wdq[1];
    #pragma unroll
    for (int mi = 0; mi < 2; mi++) {
        int r0 = m0blk + wm * 32 + mi * 16 + g;
        float x0 = g_xdq[r0], x1 = g_xdq[r0 + 8];
        float sg0 = x0 * wg, su0 = x0 * wu;
        float sg1 = x1 * wg, su1 = x1 * wu;
        #pragma unroll
        for (int ni = 0; ni < 4; ni++) {
            int c = n0blk + wn * 32 + ni * 8 + t * 2;
            float* D0 = g_h + (size_t)r0 * HDIM + c;
            float* D1 = g_h + (size_t)(r0 + 8) * HDIM + c;
            float gv, uv;
            float2 o0, o1;
            gv = accG[mi][ni][0] * sg0; uv = accU[mi][ni][0] * su0;
            o0.x = gv / (1.0f + expf(-gv)) * uv;
            gv = accG[mi][ni][1] * sg0; uv = accU[mi][ni][1] * su0;
            o0.y = gv / (1.0f + expf(-gv)) * uv;
            gv = accG[mi][ni][2] * sg1; uv = accU[mi][ni][2] * su1;
            o1.x = gv / (1.0f + expf(-gv)) * uv;
            gv = accG[mi][ni][3] * sg1; uv = accU[mi][ni][3] * su1;
            o1.y = gv / (1.0f + expf(-gv)) * uv;
            *(float2*)D0 = o0;
            *(float2*)D1 = o1;
        }
    }
}

// ---- w3 GEMM: out = hq @ w3^T (fp32 out), 256 threads, 2x4 warps, 2 CTA/SM, 4x-unrolled ----
__global__ void __launch_bounds__(256, 2) gemm_w3(float* __restrict__ outext,
        const __grid_constant__ CUtensorMap tmA,
        const __grid_constant__ CUtensorMap tmB) {
    extern __shared__ char dsm[];
    __shared__ __align__(8) uint64_t s_full[STAGES];
    __shared__ __align__(8) uint64_t s_empty[STAGES];

    int tid = threadIdx.x;
    int lane = tid & 31;
    int warp = tid >> 5;
    int wm = warp & 1;
    int wn = warp >> 1;
    int g = lane >> 2;
    int t = lane & 3;
    int grp = lane >> 3;
    int lr = lane & 7;
    int m0blk = blockIdx.y * BM;
    int n0blk = blockIdx.x * BN;
    const int NT = HDIM / BKE;   // 176 (44 unrolled blocks)

    uint32_t dbase = (uint32_t)__cvta_generic_to_shared(dsm);
    dbase = (dbase + 1023) & ~1023u;
    uint32_t fullu = (uint32_t)__cvta_generic_to_shared(&s_full[0]);
    uint32_t emptyu = (uint32_t)__cvta_generic_to_shared(&s_empty[0]);

    if (tid == 0) {
        #pragma unroll
        for (int s = 0; s < STAGES; s++) {
            MBAR_INIT(fullu + s * 8, 1);
            MBAR_INIT(emptyu + s * 8, 8);
        }
        asm volatile("fence.proxy.async.shared::cta;" ::: "memory");
    }
    __syncthreads();

    if (tid == 0) {
        #pragma unroll
        for (int s = 0; s < STAGES; s++) {
            MBAR_EXPECT(fullu + s * 8, STAGE_W3);
            uint32_t sb = dbase + s * STAGE_W3;
            TMA2D(sb, &tmA, s * BKE, m0blk, fullu + s * 8);
            TMA2D(sb + ATILE, &tmB, s * BKE, n0blk, fullu + s * 8);
        }
    }

    int aoff[2][2];
    #pragma unroll
    for (int mi = 0; mi < 2; mi++)
        #pragma unroll
        for (int ks = 0; ks < 2; ks++) {
            int row = wm * 32 + mi * 16 + lr + ((grp & 1) << 3);
            int c = ks * 2 + (grp >> 1);
            aoff[mi][ks] = row * ROWB + ((c ^ ((row >> 1) & 3)) << 4);
        }
    int boff[2][2];
    #pragma unroll
    for (int p = 0; p < 2; p++)
        #pragma unroll
        for (int ks = 0; ks < 2; ks++) {
            int row = wn * 32 + p * 16 + ((grp & 1) << 3) + lr;
            int c = ks * 2 + (grp >> 1);
            boff[p][ks] = ATILE + row * ROWB + ((c ^ ((row >> 1) & 3)) << 4);
        }

    float acc[2][4][4];
    #pragma unroll
    for (int mi = 0; mi < 2; mi++)
        #pragma unroll
        for (int ni = 0; ni < 4; ni++)
            #pragma unroll
            for (int j = 0; j < 4; j++) acc[mi][ni][j] = 0.f;

    const int NB = NT / STAGES;   // 44
    for (int kb = 0; kb < NB; kb++) {
        uint32_t par = (uint32_t)kb & 1;
        #pragma unroll
        for (int s = 0; s < STAGES; s++) {
            uint32_t sb = dbase + s * STAGE_W3;

            mbar_wait(fullu + s * 8, par);

            // ---- ks = 0 ----
            {
                uint32_t a[2][4];
                uint32_t b[2][4];
                #pragma unroll
                for (int mi = 0; mi < 2; mi++)
                    ldsm4(a[mi][0], a[mi][1], a[mi][2], a[mi][3], sb + aoff[mi][0]);
                #pragma unroll
                for (int p = 0; p < 2; p++)
                    ldsm4(b[p][0], b[p][1], b[p][2], b[p][3], sb + boff[p][0]);
                #pragma unroll
                for (int mi = 0; mi < 2; mi++)
                    #pragma unroll
                    for (int ni = 0; ni < 4; ni++)
                        mma_bf16(acc[mi][ni], a[mi],
                                 b[ni >> 1][ni & 1], b[ni >> 1][2 + (ni & 1)]);
            }
            // ---- ks = 1: loads, free stage, then MMA ----
            {
                uint32_t a[2][4];
                uint32_t b[2][4];
                #pragma unroll
                for (int mi = 0; mi < 2; mi++)
                    ldsm4(a[mi][0], a[mi][1], a[mi][2], a[mi][3], sb + aoff[mi][1]);
                #pragma unroll
                for (int p = 0; p < 2; p++)
                    ldsm4(b[p][0], b[p][1], b[p][2], b[p][3], sb + boff[p][1]);

                if (lane == 0) MBAR_ARRIVE(emptyu + s * 8);

                #pragma unroll
                for (int mi = 0; mi < 2; mi++)
                    #pragma unroll
                    for (int ni = 0; ni < 4; ni++)
                        mma_bf16(acc[mi][ni], a[mi],
                                 b[ni >> 1][ni & 1], b[ni >> 1][2 + (ni & 1)]);
            }

            int nkt = (kb + 1) * STAGES + s;
            if (tid == 0 && nkt < NT) {
                mbar_wait(emptyu + s * 8, par);
                MBAR_EXPECT(fullu + s * 8, STAGE_W3);
                TMA2D(sb, &tmA, nkt * BKE, m0blk, fullu + s * 8);
                TMA2D(sb + ATILE, &tmB, nkt * BKE, n0blk, fullu + s * 8);
            }
        }
    }

    float wq = g_wdq[2];
    #pragma unroll
    for (int mi = 0; mi < 2; mi++) {
        int r0 = m0blk + wm * 32 + mi * 16 + g;
        float s0 = g_hdq[r0] * wq;
        float s1 = g_hdq[r0 + 8] * wq;
        #pragma unroll
        for (int ni = 0; ni < 4; ni++) {
            int c = n0blk + wn * 32 + ni * 8 + t * 2;
            float* C0 = outext + (size_t)r0 * DDIM + c;
            float* C1 = outext + (size_t)(r0 + 8) * DDIM + c;
            *(float2*)C0 = make_float2(acc[mi][ni][0] * s0, acc[mi][ni][1] * s0);
            *(float2*)C1 = make_float2(acc[mi][ni][2] * s1, acc[mi][ni][3] * s1);
        }
    }
}

// ---------------- host: tensormap encode via runtime-resolved driver entry ----------------
typedef CUresult (*PFN_tmEncode)(CUtensorMap*, CUtensorMapDataType, cuuint32_t, void*,
                                 const cuuint64_t*, const cuuint64_t*, const cuuint32_t*,
                                 const cuuint32_t*, CUtensorMapInterleave, CUtensorMapSwizzle,
                                 CUtensorMapL2promotion, CUtensorMapFloatOOBfill);

static PFN_tmEncode get_encoder() {
    void* fp = nullptr;
    cudaDriverEntryPointQueryResult qr;
#if CUDART_VERSION >= 12050
    cudaGetDriverEntryPointByVersion("cuTensorMapEncodeTiled", &fp, 12000, cudaEnableDefault, &qr);
#else
    cudaGetDriverEntryPoint("cuTensorMapEncodeTiled", &fp, cudaEnableDefault, &qr);
#endif
    return (PFN_tmEncode)fp;
}

static void make_map(PFN_tmEncode enc, CUtensorMap* m, void* base, uint64_t kdim, uint64_t rows,
                     uint32_t boxRows) {
    cuuint64_t dims[2] = {kdim, rows};
    cuuint64_t strides[1] = {kdim * 2};       // bytes (bf16)
    cuuint32_t box[2] = {BKE, boxRows};
    cuuint32_t es[2] = {1, 1};
    enc(m, CU_TENSOR_MAP_DATA_TYPE_BFLOAT16, 2, base, dims, strides, box, es,
        CU_TENSOR_MAP_INTERLEAVE_NONE, CU_TENSOR_MAP_SWIZZLE_64B,
        CU_TENSOR_MAP_L2_PROMOTION_L2_128B, CU_TENSOR_MAP_FLOAT_OOB_FILL_NONE);
}

// ---------------- launch ----------------
extern "C" void kernel_launch(void* const* d_in, const int* in_sizes, int n_in,
                              void* d_out, int out_size) {
    const float* x  = (const float*)d_in[0];
    const float* w1 = (const float*)d_in[1];
    const float* w2 = (const float*)d_in[2];
    const float* w3 = (const float*)d_in[3];
    float* out = (float*)d_out;

    PFN_tmEncode enc = get_encoder();
    void *p_xq, *p_w1, *p_w2, *p_w3, *p_hq;
    cudaGetSymbolAddress(&p_xq, g_xq);
    cudaGetSymbolAddress(&p_w1, g_w1q);
    cudaGetSymbolAddress(&p_w2, g_w2q);
    cudaGetSymbolAddress(&p_w3, g_w3q);
    cudaGetSymbolAddress(&p_hq, g_hq);

    CUtensorMap tm_xq, tm_w1, tm_w2, tm_w3, tm_hq;
    make_map(enc, &tm_xq, p_xq, DDIM, MTOK, BM);
    make_map(enc, &tm_w1, p_w1, DDIM, HDIM, BN);
    make_map(enc, &tm_w2, p_w2, DDIM, HDIM, BN);
    make_map(enc, &tm_w3, p_w3, HDIM, DDIM, BN);
    make_map(enc, &tm_hq, p_hq, HDIM, MTOK, BM);

    const int smemGU = STAGES * STAGE_GU + 1024;   // 82944
    const int smemW3 = STAGES * STAGE_W3 + 1024;   // 50176
    cudaFuncSetAttribute(gemm_gateup, cudaFuncAttributeMaxDynamicSharedMemorySize, smemGU);
    cudaFuncSetAttribute(gemm_w3, cudaFuncAttributeMaxDynamicSharedMemorySize, smemW3);

    const int nW = HDIM * DDIM;
    wsum_partial_all<<<3072, 256>>>(w1, w2, w3, nW);                 // 1
    wfinal_actqx<<<MTOK + 3, 256>>>(x, nW);                          // 2
    dim3 gq((nW / 4 + 255) / 256, 3);
    wquant_all<<<gq, 256>>>(w1, w2, w3, nW / 4);                     // 3

    dim3 ggu(HDIM / BN, MTOK / BM);
    gemm_gateup<<<ggu, 256, smemGU>>>(tm_xq, tm_w1, tm_w2);          // 4

    actq_h<<<MTOK, 256>>>();                                         // 5

    dim3 gw3(DDIM / BN, MTOK / BM);
    gemm_w3<<<gw3, 256, smemW3>>>(out, tm_hq, tm_w3);                // 6
}